// round 11
// baseline (speedup 1.0000x reference)
#include <cuda_runtime.h>
#include <math.h>

#define TB    8
#define TD    512
#define TDD   1024
#define TT    4096
#define NGRP  4        // independent groups (2 batch rows each)
#define GCTA  32       // CTAs per group
#define NCTA  (NGRP * GCTA)
#define CJ    32       // h cols per CTA
#define CI    16       // p cols per CTA
#define NTHR  256
#define NWARP 8

// Row-pair packed state: [group][col][row0,row1]
__device__ float gMemP[NGRP][TD][2];     // 16 KB
__device__ float gHP[NGRP][TDD][2];      // 32 KB
__device__ float gXp[(size_t)TT * TB * TDD];   // x@W1x^T, [t][b][j]
__device__ __align__(256) unsigned gBarH[NGRP][64];
__device__ __align__(256) unsigned gBarM[NGRP][64];

__global__ void init_scratch() {
    int t = blockIdx.x * blockDim.x + threadIdx.x;
    if (t < NGRP * TD * 2) ((float*)gMemP)[t] = 0.0f;
    if (t < NGRP * 64) { ((unsigned*)gBarH)[t] = 0u; ((unsigned*)gBarM)[t] = 0u; }
}

__device__ __forceinline__ void fma2(unsigned long long& acc,
                                     unsigned long long a,
                                     unsigned long long b) {
    asm volatile("fma.rn.f32x2 %0, %1, %2, %0;" : "+l"(acc) : "l"(a), "l"(b));
}
__device__ __forceinline__ float2 u2f(unsigned long long v) {
    float2 f;
    asm("mov.b64 {%0,%1}, %2;" : "=f"(f.x), "=f"(f.y) : "l"(v));
    return f;
}
__device__ __forceinline__ unsigned long long fdup(float v) {
    unsigned long long r;
    asm("mov.b64 %0, {%1,%1};" : "=l"(r) : "f"(v));
    return r;
}
__device__ __forceinline__ ulonglong2 ldg128_cg(const void* p) {
    ulonglong2 v;
    asm volatile("ld.global.cg.v2.u64 {%0,%1}, [%2];"
                 : "=l"(v.x), "=l"(v.y) : "l"(p));
    return v;
}
__device__ __forceinline__ void stg_cg(float* p, float v) {
    asm volatile("st.global.cg.f32 [%0], %1;" :: "l"(p), "f"(v) : "memory");
}
__device__ __forceinline__ void bar_arrive(unsigned* ctr) {
    unsigned one = 1u;
    asm volatile("red.release.gpu.global.add.u32 [%0], %1;"
                 :: "l"(ctr), "r"(one) : "memory");
}
__device__ __forceinline__ void bar_spin(const unsigned* ctr, unsigned tgt) {
    unsigned v;
    do {
        asm volatile("ld.relaxed.gpu.global.u32 %0, [%1];"
                     : "=r"(v) : "l"(ctr) : "memory");
    } while (v < tgt);
}

// ======================= xproj precompute GEMM =============================
// gXp[((t*TB)+b)*TDD + j] = sum_{k<512} x[b][t][k] * W1[j][k]
#define PM 128
#define PN 64
#define PK 32

__global__ void __launch_bounds__(256, 3)
xproj_kernel(const float* __restrict__ x, const float* __restrict__ W1) {
    __shared__ float As[PK][PM];
    __shared__ unsigned long long Bs[PK][PN];

    const int tid = threadIdx.x;
    const int n0 = blockIdx.x * PN;
    const int m0 = blockIdx.y * PM;
    const int tx = tid & 15;
    const int ty = tid >> 4;

    unsigned long long acc[4][4];
#pragma unroll
    for (int a = 0; a < 4; ++a)
#pragma unroll
        for (int c = 0; c < 4; ++c) acc[a][c] = 0ull;

    for (int kt = 0; kt < 512; kt += PK) {
        __syncthreads();
        {
            const int m = tid & 127, kh = tid >> 7;
            const float* src = x + (size_t)(m0 + m) * 512 + kt + kh * 16;
#pragma unroll
            for (int q = 0; q < 4; ++q) {
                float4 v = *(const float4*)(src + q * 4);
                const int kk = kh * 16 + q * 4;
                As[kk + 0][m] = v.x; As[kk + 1][m] = v.y;
                As[kk + 2][m] = v.z; As[kk + 3][m] = v.w;
            }
        }
        {
            const int n = tid & 63, kh = tid >> 6;
            const float* src = W1 + (size_t)(n0 + n) * 1024 + kt + kh * 8;
#pragma unroll
            for (int q = 0; q < 2; ++q) {
                float4 v = *(const float4*)(src + q * 4);
                const int kk = kh * 8 + q * 4;
                Bs[kk + 0][n] = fdup(v.x); Bs[kk + 1][n] = fdup(v.y);
                Bs[kk + 2][n] = fdup(v.z); Bs[kk + 3][n] = fdup(v.w);
            }
        }
        __syncthreads();
#pragma unroll
        for (int k = 0; k < PK; ++k) {
            const ulonglong2 a01 = *(const ulonglong2*)&As[k][ty * 8];
            const ulonglong2 a23 = *(const ulonglong2*)&As[k][ty * 8 + 4];
            const ulonglong2 b01 = *(const ulonglong2*)&Bs[k][tx * 4];
            const ulonglong2 b23 = *(const ulonglong2*)&Bs[k][tx * 4 + 2];
            fma2(acc[0][0], a01.x, b01.x); fma2(acc[0][1], a01.x, b01.y);
            fma2(acc[0][2], a01.x, b23.x); fma2(acc[0][3], a01.x, b23.y);
            fma2(acc[1][0], a01.y, b01.x); fma2(acc[1][1], a01.y, b01.y);
            fma2(acc[1][2], a01.y, b23.x); fma2(acc[1][3], a01.y, b23.y);
            fma2(acc[2][0], a23.x, b01.x); fma2(acc[2][1], a23.x, b01.y);
            fma2(acc[2][2], a23.x, b23.x); fma2(acc[2][3], a23.x, b23.y);
            fma2(acc[3][0], a23.y, b01.x); fma2(acc[3][1], a23.y, b01.y);
            fma2(acc[3][2], a23.y, b23.x); fma2(acc[3][3], a23.y, b23.y);
        }
    }
#pragma unroll
    for (int mp = 0; mp < 4; ++mp) {
        const int m_even = ty * 8 + mp * 2;
#pragma unroll
        for (int par = 0; par < 2; ++par) {
            const int r = m0 + m_even + par;
            const int t = r & 4095, b = r >> 12;
            float4 v;
            v.x = par ? u2f(acc[mp][0]).y : u2f(acc[mp][0]).x;
            v.y = par ? u2f(acc[mp][1]).y : u2f(acc[mp][1]).x;
            v.z = par ? u2f(acc[mp][2]).y : u2f(acc[mp][2]).x;
            v.w = par ? u2f(acc[mp][3]).y : u2f(acc[mp][3]).x;
            *(float4*)(gXp + ((size_t)t * TB + b) * TDD + n0 + tx * 4) = v;
        }
    }
}

// ======================= sequential recurrence kernel ======================
// Group g = cta>>5 owns batch rows {2g, 2g+1}. CTA c = cta&31:
//   GEMM1: h[rows][c*32 .. +32)   GEMM2: p[rows][c*16 .. +16)
__global__ void __launch_bounds__(NTHR, 1)
sys2_kernel(const float* __restrict__ W1,
            const float* __restrict__ b1,
            const float* __restrict__ W2,
            const float* __restrict__ b2,
            float* __restrict__ y)
{
    extern __shared__ float smem[];
    float* sW1m = smem;                            // CJ*TD   (64 KB)
    float* sW2  = sW1m + CJ * TD;                  // CI*TDD  (64 KB)
    unsigned long long* sP1 =
        (unsigned long long*)(sW2 + CI * TDD);     // 8*32 ull (2 KB) rowpair
    unsigned long long* sP2 = sP1 + NWARP * CJ;    // 8*16 ull (1 KB)
    float* sB1 = (float*)(sP2 + NWARP * CI);       // CJ
    float* sB2 = sB1 + CJ;                         // CI

    const int cta  = blockIdx.x;
    const int g    = cta >> 5;
    const int c    = cta & 31;
    const int tid  = threadIdx.x;
    const int w    = tid >> 5;
    const int lane = tid & 31;
    const int kq   = lane & 7;    // k-phase (8 per warp)
    const int jq   = lane >> 3;   // col-quarter (4 per warp)
    const int jbase = c * CJ;
    const int ibase = c * CI;

    {   // stage weight slices
        float4* s1 = (float4*)sW1m;
        for (int idx = tid; idx < CJ * TD / 4; idx += NTHR) {
            const int j = idx >> 7, kf = idx & 127;   // TD/4 = 128 float4/row
            s1[idx] = *(const float4*)(W1 + (size_t)(jbase + j) * TDD + TD + kf * 4);
        }
        const float4* g2 = (const float4*)(W2 + (size_t)ibase * TDD);
        float4* s2 = (float4*)sW2;
        for (int idx = tid; idx < CI * TDD / 4; idx += NTHR) s2[idx] = g2[idx];
        if (tid < CJ) sB1[tid] = b1[jbase + tid];
        if (tid < CI) sB2[tid] = b2[ibase + tid];
    }
    __syncthreads();

    float memReg = 0.0f;   // tid<32 owns (row = 2g+(tid>>4), col = ibase+(tid&15))

    // preload xq(0): thread o<64 -> row 2g+(o>>5), j = jbase+(o&31)
    float xq = 0.0f;
    if (tid < 2 * CJ)
        xq = __ldg(&gXp[((size_t)0 * TB + (2 * g + (tid >> 5))) * TDD + jbase + (tid & 31)]);

    const unsigned* barM = &gBarM[g][0];
    const unsigned* barH = &gBarH[g][0];

    for (int t = 0; t < TT; ++t) {
        // ===== Phase 1: h = gelu(W1m @ mem + xq + b1) =====
        if (t > 0 && tid == 0) bar_spin(barM, (unsigned)t * GCTA);
        __syncthreads();                       // S1: group mem(t-1) visible

        // mem row-pairs: k1..k1+7 (4 x 16B, each = 2 k of both rows)
        const int k1 = (w << 6) + (kq << 3);
        ulonglong2 em[4];
#pragma unroll
        for (int q = 0; q < 4; ++q)
            em[q] = ldg128_cg(&gMemP[g][k1 + 2 * q][0]);

        unsigned long long ac[8];
#pragma unroll
        for (int j = 0; j < 8; ++j) ac[j] = 0ull;
#pragma unroll
        for (int j = 0; j < 8; ++j) {
            const int jj = (jq << 3) + j;
            const float4 w0 = *(const float4*)(sW1m + jj * TD + k1);
            const float4 w1 = *(const float4*)(sW1m + jj * TD + k1 + 4);
            fma2(ac[j], fdup(w0.x), em[0].x);
            fma2(ac[j], fdup(w0.y), em[0].y);
            fma2(ac[j], fdup(w0.z), em[1].x);
            fma2(ac[j], fdup(w0.w), em[1].y);
            fma2(ac[j], fdup(w1.x), em[2].x);
            fma2(ac[j], fdup(w1.y), em[2].y);
            fma2(ac[j], fdup(w1.z), em[3].x);
            fma2(ac[j], fdup(w1.w), em[3].y);
        }
        // reduce over kq lanes (bits 0..2), keep rowpair packed
#pragma unroll
        for (int j = 0; j < 8; ++j) {
            unsigned long long v = ac[j];
            float2 f = u2f(v);
            f.x += __shfl_xor_sync(0xffffffffu, f.x, 1);
            f.y += __shfl_xor_sync(0xffffffffu, f.y, 1);
            f.x += __shfl_xor_sync(0xffffffffu, f.x, 2);
            f.y += __shfl_xor_sync(0xffffffffu, f.y, 2);
            f.x += __shfl_xor_sync(0xffffffffu, f.x, 4);
            f.y += __shfl_xor_sync(0xffffffffu, f.y, 4);
            if (kq == 0) {
                unsigned long long pk;
                asm("mov.b64 %0, {%1,%2};" : "=l"(pk) : "f"(f.x), "f"(f.y));
                sP1[(w << 5) + (jq << 3) + j] = pk;
            }
        }
        __syncthreads();                       // S2

        // h-epilogue: threads 0..63 -> (row r = o>>5, col j = o&31)
        if (tid < 2 * CJ) {
            const int r = tid >> 5, j = tid & 31;
            float s = sB1[j] + xq;
#pragma unroll
            for (int ww = 0; ww < NWARP; ++ww) {
                const float2 f = u2f(sP1[(ww << 5) + j]);
                s += r ? f.y : f.x;
            }
            const float hval = 0.5f * s * (1.0f + erff(s * 0.70710678118654752f));
            stg_cg(&gHP[g][jbase + j][r], hval);
        }
        __syncthreads();                       // S2b
        if (tid == 0) bar_arrive(&gBarH[g][0]);

        // prefetch xq(t+1) — overlaps h-wait + GEMM2
        if (tid < 2 * CJ) {
            const int tn = (t + 1 < TT) ? (t + 1) : t;
            xq = __ldg(&gXp[((size_t)tn * TB + (2 * g + (tid >> 5))) * TDD + jbase + (tid & 31)]);
        }

        if (tid == 0) bar_spin(barH, (unsigned)(t + 1) * GCTA);
        __syncthreads();                       // S3: group h(t) visible

        // ===== Phase 2: p = W2 @ h + b2 ; gated mem update =====
        const int k2 = (w << 7) + (kq << 4);   // 16 k per lane
        ulonglong2 eh[8];
#pragma unroll
        for (int q = 0; q < 8; ++q)
            eh[q] = ldg128_cg(&gHP[g][k2 + 2 * q][0]);

        unsigned long long pc[4];
#pragma unroll
        for (int i = 0; i < 4; ++i) pc[i] = 0ull;
#pragma unroll
        for (int i = 0; i < 4; ++i) {
            const int ii = (jq << 2) + i;
            const float* wr = sW2 + ii * TDD + k2;
#pragma unroll
            for (int q = 0; q < 4; ++q) {
                const float4 wv = *(const float4*)(wr + 4 * q);
                fma2(pc[i], fdup(wv.x), eh[2 * q].x);
                fma2(pc[i], fdup(wv.y), eh[2 * q].y);
                fma2(pc[i], fdup(wv.z), eh[2 * q + 1].x);
                fma2(pc[i], fdup(wv.w), eh[2 * q + 1].y);
            }
        }
#pragma unroll
        for (int i = 0; i < 4; ++i) {
            float2 f = u2f(pc[i]);
            f.x += __shfl_xor_sync(0xffffffffu, f.x, 1);
            f.y += __shfl_xor_sync(0xffffffffu, f.y, 1);
            f.x += __shfl_xor_sync(0xffffffffu, f.x, 2);
            f.y += __shfl_xor_sync(0xffffffffu, f.y, 2);
            f.x += __shfl_xor_sync(0xffffffffu, f.x, 4);
            f.y += __shfl_xor_sync(0xffffffffu, f.y, 4);
            if (kq == 0) {
                unsigned long long pk;
                asm("mov.b64 %0, {%1,%2};" : "=l"(pk) : "f"(f.x), "f"(f.y));
                sP2[(w << 4) + (jq << 2) + i] = pk;
            }
        }
        __syncthreads();                       // S4

        // mem-epilogue: threads 0..31 -> (row r = o>>4, col i = o&15)
        if (tid < 2 * CI) {
            const int r = tid >> 4, i = tid & 15;
            float p = sB2[i];
#pragma unroll
            for (int ww = 0; ww < NWARP; ++ww) {
                const float2 f = u2f(sP2[(ww << 4) + i]);
                p += r ? f.y : f.x;
            }
            const float gg = 1.0f / (1.0f + expf(-p));
            memReg = fmaf(p - memReg, gg, memReg);
            stg_cg(&gMemP[g][ibase + i][r], memReg);
            y[((size_t)(2 * g + r) * TT + t) * TD + ibase + i] = memReg;
        }
        __syncthreads();                       // S4b
        if (tid == 0) bar_arrive(&gBarM[g][0]);
    }
}

extern "C" void kernel_launch(void* const* d_in, const int* in_sizes, int n_in,
                              void* d_out, int out_size) {
    const float* x  = (const float*)d_in[0];
    const float* W1 = (const float*)d_in[1];
    const float* b1 = (const float*)d_in[2];
    const float* W2 = (const float*)d_in[3];
    const float* b2 = (const float*)d_in[4];
    float* y = (float*)d_out;

    const size_t SMEM_BYTES =
        (CJ * TD + CI * TDD) * sizeof(float) +
        (NWARP * CJ + NWARP * CI) * sizeof(unsigned long long) +
        (CJ + CI) * sizeof(float);
    cudaFuncSetAttribute(sys2_kernel,
                         cudaFuncAttributeMaxDynamicSharedMemorySize,
                         (int)SMEM_BYTES);

    init_scratch<<<(NGRP * TD * 2 + 255) / 256, 256>>>();
    xproj_kernel<<<dim3(TDD / PN, (TB * TT) / PM), 256>>>(x, W1);
    sys2_kernel<<<NCTA, NTHR, SMEM_BYTES>>>(W1, b1, W2, b2, y);
}

// round 12
// speedup vs baseline: 1.3024x; 1.3024x over previous
#include <cuda_runtime.h>
#include <math.h>

#define TB   8
#define TD   512
#define TDD  1024
#define TT   4096
#define NCTA 128
#define CJ   8        // h cols per CTA
#define CI   4        // p cols per CTA
#define NTHR 256
#define NWARP 8

__device__ float gMem[TB * TD];    // recurrent state (in place; schedule-proven safe)
__device__ float gH[TB * TDD];     // hidden activations (in place)
__device__ __align__(256) unsigned gBarH[64];   // arrivals after h(t) published
__device__ __align__(256) unsigned gBarM[64];   // arrivals after mem(t) published

__global__ void init_scratch() {
    int t = blockIdx.x * blockDim.x + threadIdx.x;
    if (t < TB * TD) gMem[t] = 0.0f;
    if (t < 64) { gBarH[t] = 0u; gBarM[t] = 0u; }
}

__device__ __forceinline__ void fma2(unsigned long long& acc,
                                     unsigned long long a,
                                     unsigned long long b) {
    asm volatile("fma.rn.f32x2 %0, %1, %2, %0;" : "+l"(acc) : "l"(a), "l"(b));
}
__device__ __forceinline__ float2 u2f(unsigned long long v) {
    float2 f;
    asm("mov.b64 {%0,%1}, %2;" : "=f"(f.x), "=f"(f.y) : "l"(v));
    return f;
}
__device__ __forceinline__ ulonglong2 ldg128_cg(const void* p) {
    ulonglong2 v;
    asm volatile("ld.global.cg.v2.u64 {%0,%1}, [%2];"
                 : "=l"(v.x), "=l"(v.y) : "l"(p));
    return v;
}
__device__ __forceinline__ ulonglong2 ldg128_nc(const void* p) {
    ulonglong2 v;
    asm volatile("ld.global.nc.v2.u64 {%0,%1}, [%2];"
                 : "=l"(v.x), "=l"(v.y) : "l"(p));
    return v;
}
__device__ __forceinline__ void stg_cg(float* p, float v) {
    asm volatile("st.global.cg.f32 [%0], %1;" :: "l"(p), "f"(v) : "memory");
}
// cumulative-release arrive (after __syncthreads: publishes the CTA's prior stores)
__device__ __forceinline__ void bar_arrive(unsigned* ctr) {
    unsigned one = 1u;
    asm volatile("red.release.gpu.global.add.u32 [%0], %1;"
                 :: "l"(ctr), "r"(one) : "memory");
}
// warp-converged spin on one counter word (all 32 lanes load same word)
__device__ __forceinline__ void bar_spin_warp(const unsigned* ctr, unsigned tgt) {
    unsigned v;
    do {
        asm volatile("ld.relaxed.gpu.global.u32 %0, [%1];"
                     : "=r"(v) : "l"(ctr) : "memory");
    } while (__any_sync(0xffffffffu, v < tgt));
}
// hot busy-wait on SMEM generation word: dense dummy FMA issue keeps the SM
// out of the low-power state while waiting (DVFS countermeasure).
__device__ __forceinline__ void busy_wait(volatile unsigned* g, unsigned tgt) {
    float d0 = 1.0f, d1 = 1.0f, d2 = 1.0f, d3 = 1.0f;
    while (*g < tgt) {
#pragma unroll
        for (int q = 0; q < 6; ++q) {
            asm volatile("fma.rn.f32 %0, %0, %1, %2;" : "+f"(d0) : "f"(1.0000001f), "f"(1e-30f));
            asm volatile("fma.rn.f32 %0, %0, %1, %2;" : "+f"(d1) : "f"(1.0000001f), "f"(1e-30f));
            asm volatile("fma.rn.f32 %0, %0, %1, %2;" : "+f"(d2) : "f"(1.0000001f), "f"(1e-30f));
            asm volatile("fma.rn.f32 %0, %0, %1, %2;" : "+f"(d3) : "f"(1.0000001f), "f"(1e-30f));
        }
    }
}

__global__ void __launch_bounds__(NTHR, 1)
sys2_kernel(const float* __restrict__ x,
            const float* __restrict__ W1,
            const float* __restrict__ b1,
            const float* __restrict__ W2,
            const float* __restrict__ b2,
            float* __restrict__ y)
{
    extern __shared__ float smem[];
    float* sW1   = smem;                     // CJ*TDD (32 KB)
    float* sW2   = sW1 + CJ * TDD;           // CI*TDD (16 KB)
    float* sPart = sW2 + CI * TDD;           // NWARP*64 = 512
    float* sB1   = sPart + NWARP * 64;       // CJ
    float* sB2   = sB1 + CJ;                 // CI
    __shared__ volatile unsigned sGenM;      // poller -> workers: mem(t-1) ready
    __shared__ volatile unsigned sGenH;      // poller -> workers: h(t) ready

    const int cta  = blockIdx.x;
    const int tid  = threadIdx.x;
    const int w    = tid >> 5;
    const int lane = tid & 31;
    const int b    = lane >> 2;
    const int kq   = lane & 3;
    const int jbase = cta * CJ;
    const int ibase = cta * CI;

    {
        const float4* g1 = (const float4*)(W1 + (size_t)jbase * TDD);
        float4* s1 = (float4*)sW1;
        for (int idx = tid; idx < CJ * TDD / 4; idx += NTHR) s1[idx] = g1[idx];
        const float4* g2 = (const float4*)(W2 + (size_t)ibase * TDD);
        float4* s2 = (float4*)sW2;
        for (int idx = tid; idx < CI * TDD / 4; idx += NTHR) s2[idx] = g2[idx];
        if (tid < CJ) sB1[tid] = b1[jbase + tid];
        if (tid < CI) sB2[tid] = b2[ibase + tid];
        if (tid == 0) { sGenM = 0u; sGenH = 0u; }
    }
    __syncthreads();

    float memReg = 0.0f;   // tid<32 owns output (bb=tid>>2, ii=tid&3)

    ulonglong2 ex[4];
    {
        const float* xr = x + ((size_t)b * TT) * TD;
#pragma unroll
        for (int it = 0; it < 4; ++it)
            ex[it] = ldg128_nc(xr + (w << 6) + (it << 4) + (kq << 2));
    }

    for (int t = 0; t < TT; ++t) {
        // ===== Phase 1: h = gelu(W1 @ [x_t ; mem] + b1), j-slice =====
        unsigned long long ax[CJ], ay[CJ];
#pragma unroll
        for (int j = 0; j < CJ; ++j) { ax[j] = 0ull; ay[j] = 0ull; }

        // x-half part A (independent of mem) — before the wait
#pragma unroll
        for (int it = 0; it < 2; ++it) {
            const int k = (w << 6) + (it << 4) + (kq << 2);
#pragma unroll
            for (int j = 0; j < CJ; ++j) {
                const ulonglong2 wv = *(const ulonglong2*)(sW1 + j * TDD + k);
                fma2(ax[j], wv.x, ex[it].x);
                fma2(ay[j], wv.y, ex[it].y);
            }
        }

        // ---- mem(t-1) wait: warp 7 polls L2; warps 0-6 stay HOT on SMEM gen ----
        if (w == 7) {
            if (t > 0) bar_spin_warp(&gBarM[0], (unsigned)t * NCTA);
            __syncwarp();
            if (lane == 0) sGenM = (unsigned)t;
            __syncwarp();
        } else {
            busy_wait(&sGenM, (unsigned)t);
        }

        // mem loads in flight under x-half part B
        const float* mrow = gMem + b * TD;
        ulonglong2 em[4];
#pragma unroll
        for (int it = 0; it < 4; ++it)
            em[it] = ldg128_cg(mrow + (w << 6) + (it << 4) + (kq << 2));

#pragma unroll
        for (int it = 2; it < 4; ++it) {
            const int k = (w << 6) + (it << 4) + (kq << 2);
#pragma unroll
            for (int j = 0; j < CJ; ++j) {
                const ulonglong2 wv = *(const ulonglong2*)(sW1 + j * TDD + k);
                fma2(ax[j], wv.x, ex[it].x);
                fma2(ay[j], wv.y, ex[it].y);
            }
        }
#pragma unroll
        for (int it = 0; it < 4; ++it) {
            const int k = (w << 6) + (it << 4) + (kq << 2);
#pragma unroll
            for (int j = 0; j < CJ; ++j) {
                const ulonglong2 wv = *(const ulonglong2*)(sW1 + j * TDD + TD + k);
                fma2(ax[j], wv.x, em[it].x);
                fma2(ay[j], wv.y, em[it].y);
            }
        }
#pragma unroll
        for (int j = 0; j < CJ; ++j) {
            const float2 fx = u2f(ax[j]);
            const float2 fy = u2f(ay[j]);
            float s = (fx.x + fx.y) + (fy.x + fy.y);
            s += __shfl_xor_sync(0xffffffffu, s, 1);
            s += __shfl_xor_sync(0xffffffffu, s, 2);
            if (kq == 0) sPart[(w << 6) + (b << 3) + j] = s;
        }
        __syncthreads();                       // S2

        // h-epilogue: threads 0..63, 1 output each
        if (tid < TB * CJ) {
            const int bb = tid >> 3, jj = tid & 7;
            float s = sB1[jj];
#pragma unroll
            for (int ww = 0; ww < NWARP; ++ww) s += sPart[(ww << 6) + tid];
            const float hval = 0.5f * s * (1.0f + erff(s * 0.70710678118654752f));
            stg_cg(&gH[bb * TDD + jbase + jj], hval);
        }
        __syncthreads();                       // S2b: h stores done CTA-wide
        if (tid == 0) bar_arrive(&gBarH[0]);

        // prefetch x(t+1) — independent work before the h-wait
        {
            const int tn = (t + 1 < TT) ? (t + 1) : t;
            const float* xr = x + ((size_t)b * TT + tn) * TD;
#pragma unroll
            for (int it = 0; it < 4; ++it)
                ex[it] = ldg128_nc(xr + (w << 6) + (it << 4) + (kq << 2));
        }

        // ---- h(t) wait: warp 7 polls L2; warps 0-6 stay HOT ----
        if (w == 7) {
            bar_spin_warp(&gBarH[0], (unsigned)(t + 1) * NCTA);
            __syncwarp();
            if (lane == 0) sGenH = (unsigned)(t + 1);
            __syncwarp();
        } else {
            busy_wait(&sGenH, (unsigned)(t + 1));
        }

        // ===== Phase 2: p = W2 @ h + b2 ; gated mem update, i-slice =====
        const float* hrow = gH + b * TDD;
        ulonglong2 eh[8];
#pragma unroll
        for (int it = 0; it < 8; ++it)
            eh[it] = ldg128_cg(hrow + (w << 7) + (it << 4) + (kq << 2));

        unsigned long long px[CI], py[CI];
#pragma unroll
        for (int i = 0; i < CI; ++i) { px[i] = 0ull; py[i] = 0ull; }
#pragma unroll
        for (int it = 0; it < 8; ++it) {
            const int k = (w << 7) + (it << 4) + (kq << 2);
#pragma unroll
            for (int i = 0; i < CI; ++i) {
                const ulonglong2 wv = *(const ulonglong2*)(sW2 + i * TDD + k);
                fma2(px[i], wv.x, eh[it].x);
                fma2(py[i], wv.y, eh[it].y);
            }
        }
#pragma unroll
        for (int i = 0; i < CI; ++i) {
            const float2 fx = u2f(px[i]);
            const float2 fy = u2f(py[i]);
            float s = (fx.x + fx.y) + (fy.x + fy.y);
            s += __shfl_xor_sync(0xffffffffu, s, 1);
            s += __shfl_xor_sync(0xffffffffu, s, 2);
            if (kq == 0) sPart[(w << 5) + (b << 2) + i] = s;
        }
        __syncthreads();                       // S4

        // mem-epilogue: threads 0..31, 1 output each
        if (tid < TB * CI) {
            const int bb = tid >> 2, ii = tid & 3;
            float p = sB2[ii];
#pragma unroll
            for (int ww = 0; ww < NWARP; ++ww) p += sPart[(ww << 5) + tid];
            const float g = 1.0f / (1.0f + expf(-p));
            memReg = fmaf(p - memReg, g, memReg);
            stg_cg(&gMem[bb * TD + ibase + ii], memReg);
            y[((size_t)bb * TT + t) * TD + ibase + ii] = memReg;
        }
        __syncthreads();                       // S4b: mem stores done CTA-wide
        if (tid == 0) bar_arrive(&gBarM[0]);
    }
}

extern "C" void kernel_launch(void* const* d_in, const int* in_sizes, int n_in,
                              void* d_out, int out_size) {
    const float* x  = (const float*)d_in[0];
    const float* W1 = (const float*)d_in[1];
    const float* b1 = (const float*)d_in[2];
    const float* W2 = (const float*)d_in[3];
    const float* b2 = (const float*)d_in[4];
    float* y = (float*)d_out;

    const size_t SMEM_BYTES =
        (CJ * TDD + CI * TDD + NWARP * 64 + CJ + CI) * sizeof(float);
    cudaFuncSetAttribute(sys2_kernel,
                         cudaFuncAttributeMaxDynamicSharedMemorySize,
                         (int)SMEM_BYTES);

    init_scratch<<<(TB * TD + 255) / 256, 256>>>();
    sys2_kernel<<<NCTA, NTHR, SMEM_BYTES>>>(x, W1, b1, W2, b2, y);
}